// round 2
// baseline (speedup 1.0000x reference)
#include <cuda_runtime.h>
#include <cuda_bf16.h>
#include <math.h>

#define N_NODES 100000
#define N_EDGES 1600000
#define C 64
#define MAXL 4096          // max in-degree of a pair node (Poisson(16) -> hugely safe)
#define MAXF 8200          // max frontier = 2 + 2*MAXL
#define MAXA 192           // max in-degree of a frontier node (Poisson(16))

// ---------------- device scratch (static, allocation-free) ----------------
__device__ int   g_is32;               // 1 if edge/pair data is int32, 0 if int64
__device__ int   g_deg[N_NODES];
__device__ float g_dinv[N_NODES];
__device__ int   g_slot[N_NODES];      // -1 = not in frontier, else slot id
__device__ int   g_listA[MAXL];
__device__ int   g_listB[MAXL];
__device__ int   g_cntA, g_cntB, g_nfront;
__device__ int   g_frontier[MAXF];
__device__ int   g_adjcnt[MAXF];
__device__ int   g_adj[MAXF * MAXA];
__device__ float g_h1[MAXF * C];
__device__ float g_h2[2 * C];

// Flag-dispatched index accessor (edge buffer may be int32 or int64)
__device__ __forceinline__ int idx_at(const void* p, long long i, int is32) {
    if (is32) return ((const int*)p)[i];
    return (int)(((const long long*)p)[i]);
}

// ---------------- K-1: sniff dtype of edge_index ----------------
__global__ void k_sniff(const void* edge) {
    if (threadIdx.x == 0) {
        const long long* e = (const long long*)edge;
        int is32 = 0;
        #pragma unroll
        for (int i = 0; i < 16; i++) {
            long long v = e[i];
            if (v < 0 || v >= N_NODES) { is32 = 1; break; }
        }
        g_is32 = is32;
    }
}

// ---------------- K0: reset per-launch state ----------------
__global__ void k_init() {
    int i = blockIdx.x * blockDim.x + threadIdx.x;
    if (i < N_NODES) { g_deg[i] = 0; g_slot[i] = -1; }
    if (i < MAXF) g_adjcnt[i] = 0;
    if (i == 0) { g_cntA = 0; g_cntB = 0; g_nfront = 0; }
}

// ---------------- K1: scan dst -> deg counts + level-1 neighbor lists ----
__global__ void k_scan1(const void* __restrict__ edge,
                        const void* __restrict__ pair) {
    int is32 = g_is32;
    int p0 = idx_at(pair, 0, is32);
    int p1 = idx_at(pair, 1, is32);
    long long i = blockIdx.x * (long long)blockDim.x + threadIdx.x;
    if (i >= N_EDGES) return;
    int d = idx_at(edge, (long long)N_EDGES + i, is32);
    if ((unsigned)d >= N_NODES) return;      // safety: never crash
    atomicAdd(&g_deg[d], 1);
    if (d == p0 || d == p1) {
        int s = idx_at(edge, i, is32);
        if ((unsigned)s >= N_NODES) return;
        if (d == p0) {
            int k = atomicAdd(&g_cntA, 1);
            if (k < MAXL) g_listA[k] = s;
        }
        if (d == p1) {
            int k = atomicAdd(&g_cntB, 1);
            if (k < MAXL) g_listB[k] = s;
        }
    }
}

// ---------------- K2a: dinv = rsqrt(deg + 1 self loop) ----------------
__global__ void k_dinv() {
    int i = blockIdx.x * blockDim.x + threadIdx.x;
    if (i < N_NODES) g_dinv[i] = rsqrtf((float)(g_deg[i] + 1));
}

// ---------------- K2b: build deduped frontier ----------------
__global__ void k_front(const void* __restrict__ pair) {
    int is32 = g_is32;
    int cA = min(g_cntA, MAXL);
    int cB = min(g_cntB, MAXL);
    int total = 2 + cA + cB;
    for (int i = threadIdx.x; i < total; i += blockDim.x) {
        int v;
        if (i == 0)           v = idx_at(pair, 0, is32);
        else if (i == 1)      v = idx_at(pair, 1, is32);
        else if (i - 2 < cA)  v = g_listA[i - 2];
        else                  v = g_listB[i - 2 - cA];
        if ((unsigned)v >= N_NODES) continue;
        if (atomicCAS(&g_slot[v], -1, -2) == -1) {
            int s = atomicAdd(&g_nfront, 1);
            if (s < MAXF) g_frontier[s] = v;
            g_slot[v] = s;
        }
    }
}

// ---------------- K3: scan dst -> adjacency of frontier nodes ----------
__global__ void k_scan2(const void* __restrict__ edge) {
    int is32 = g_is32;
    long long i = blockIdx.x * (long long)blockDim.x + threadIdx.x;
    if (i >= N_EDGES) return;
    int d = idx_at(edge, (long long)N_EDGES + i, is32);
    if ((unsigned)d >= N_NODES) return;
    int sl = g_slot[d];
    if (sl >= 0 && sl < MAXF) {
        int s = idx_at(edge, i, is32);
        if ((unsigned)s >= N_NODES) return;
        int k = atomicAdd(&g_adjcnt[sl], 1);
        if (k < MAXA) g_adj[sl * MAXA + k] = s;
    }
}

// ---------------- K4: layer-1 GCN for frontier nodes ----------------
// h1[v] = relu( (sum_{u in N(v)} dinv[u]*dinv[v]*x[u] + dinv[v]^2*x[v]) @ W1 + b1 )
// (aggregation commutes with the linear map, so aggregate x first, then 64x64 matvec)
__global__ void k_layer1(const float* __restrict__ x,
                         const float* __restrict__ W1,
                         const float* __restrict__ b1) {
    int s = blockIdx.x;
    if (s >= g_nfront || s >= MAXF) return;
    int v = g_frontier[s];
    float dv = g_dinv[v];
    int c = threadIdx.x;                       // 64 threads = one channel each
    float y = dv * dv * __ldg(&x[(size_t)v * C + c]);
    int cnt = min(g_adjcnt[s], MAXA);
    for (int j = 0; j < cnt; j++) {
        int u = g_adj[s * MAXA + j];
        y += g_dinv[u] * dv * __ldg(&x[(size_t)u * C + c]);
    }
    __shared__ float sy[C];
    sy[c] = y;
    __syncthreads();
    float acc = b1[c];
    #pragma unroll
    for (int k = 0; k < C; k++) acc += sy[k] * W1[k * C + c];
    g_h1[s * C + c] = fmaxf(acc, 0.0f);
}

// ---------------- K5: layer-2 GCN for the two pair nodes ----------------
__global__ void k_layer2(const void* __restrict__ pair,
                         const float* __restrict__ W2,
                         const float* __restrict__ b2) {
    int is32 = g_is32;
    int p = blockIdx.x;                        // 0 or 1
    int v = idx_at(pair, p, is32);
    if ((unsigned)v >= N_NODES) return;
    float dv = g_dinv[v];
    int c = threadIdx.x;
    int sv = g_slot[v];
    float z = 0.0f;
    if (sv >= 0 && sv < MAXF) z = dv * dv * g_h1[sv * C + c];
    int cnt = (p == 0) ? min(g_cntA, MAXL) : min(g_cntB, MAXL);
    const int* list = (p == 0) ? g_listA : g_listB;
    for (int j = 0; j < cnt; j++) {
        int u = list[j];
        int su = g_slot[u];
        if (su >= 0 && su < MAXF)
            z += g_dinv[u] * dv * g_h1[su * C + c];
    }
    __shared__ float sz[C];
    sz[c] = z;
    __syncthreads();
    float acc = b2[c];
    #pragma unroll
    for (int k = 0; k < C; k++) acc += sz[k] * W2[k * C + c];
    g_h2[p * C + c] = fmaxf(acc, 0.0f);
}

// ---------------- K6: final dot + sigmoid ----------------
__global__ void k_final(const float* __restrict__ fcW,
                        const float* __restrict__ fcb,
                        float* __restrict__ out) {
    int t = threadIdx.x;                       // 128 threads
    __shared__ float red[2 * C];
    red[t] = g_h2[t] * fcW[t];
    __syncthreads();
    for (int s = C; s > 0; s >>= 1) {
        if (t < s) red[t] += red[t + s];
        __syncthreads();
    }
    if (t == 0) out[0] = 1.0f / (1.0f + expf(-(red[0] + fcb[0])));
}

// ---------------- launch ----------------
extern "C" void kernel_launch(void* const* d_in, const int* in_sizes, int n_in,
                              void* d_out, int out_size) {
    const float* x    = (const float*)d_in[0];
    const void*  edge = d_in[1];
    const void*  pair = d_in[2];
    const float* W1   = (const float*)d_in[3];
    const float* b1   = (const float*)d_in[4];
    const float* W2   = (const float*)d_in[5];
    const float* b2   = (const float*)d_in[6];
    const float* fcW  = (const float*)d_in[7];
    const float* fcb  = (const float*)d_in[8];
    float* out = (float*)d_out;

    k_sniff<<<1, 32>>>(edge);
    k_init<<<(N_NODES + 511) / 512, 512>>>();
    k_scan1<<<(N_EDGES + 255) / 256, 256>>>(edge, pair);
    k_dinv<<<(N_NODES + 511) / 512, 512>>>();
    k_front<<<1, 512>>>(pair);
    k_scan2<<<(N_EDGES + 255) / 256, 256>>>(edge);
    k_layer1<<<MAXF, C>>>(x, W1, b1);
    k_layer2<<<2, C>>>(pair, W2, b2);
    k_final<<<1, 2 * C>>>(fcW, fcb, out);
}

// round 3
// speedup vs baseline: 1.7915x; 1.7915x over previous
#include <cuda_runtime.h>
#include <cuda_bf16.h>
#include <math.h>

#define N_NODES 100000
#define N_EDGES 1600000
#define C 64
#define MAXL 512           // max in-degree of a pair node (Poisson(16): p(>512)~0)
#define MAXF 1026          // 2 + 2*MAXL
#define EPT 4              // edges per thread in scans

// ---------------- device scratch (static, allocation-free) ----------------
__device__ int   g_is32;               // 1 if edge/pair data is int32, 0 if int64
__device__ int   g_deg[N_NODES];
__device__ int   g_slot[N_NODES];      // -1 = not in frontier, else slot id
__device__ int   g_listA[MAXL];
__device__ int   g_listB[MAXL];
__device__ int   g_cntA, g_cntB, g_nfront;
__device__ int   g_frontier[MAXF];
__device__ float g_agg[MAXF * C];      // sum over in-edges of dinv[src]*x[src]
__device__ float g_h1[MAXF * C];
__device__ float g_h2[2 * C];

__device__ __forceinline__ int idx_at(const void* p, long long i, int is32) {
    if (is32) return ((const int*)p)[i];
    return (int)(((const long long*)p)[i]);
}

__device__ __forceinline__ void fr_insert(int v) {
    if ((unsigned)v >= N_NODES) return;
    if (atomicCAS(&g_slot[v], -1, -2) == -1) {
        int s = atomicAdd(&g_nfront, 1);
        if (s < MAXF) { g_frontier[s] = v; g_slot[v] = s; }
    }
}

// ---------------- K0: init + dtype sniff ----------------
__global__ void k_init(const void* __restrict__ edge) {
    int i = blockIdx.x * blockDim.x + threadIdx.x;
    if (i < N_NODES) { g_deg[i] = 0; g_slot[i] = -1; }
    if (i < MAXF * C) g_agg[i] = 0.0f;
    if (i == 0) {
        g_cntA = 0; g_cntB = 0; g_nfront = 0;
        const long long* e = (const long long*)edge;
        int is32 = 0;
        #pragma unroll
        for (int k = 0; k < 16; k++) {
            long long v = e[k];
            if (v < 0 || v >= N_NODES) { is32 = 1; break; }
        }
        g_is32 = is32;
    }
}

// ---------------- K1: scan dst -> degrees + pair lists + frontier ----------
__global__ void k_scan1(const void* __restrict__ edge,
                        const void* __restrict__ pair) {
    int is32 = g_is32;
    int p0 = idx_at(pair, 0, is32);
    int p1 = idx_at(pair, 1, is32);
    int gt = blockIdx.x * blockDim.x + threadIdx.x;
    if (gt < 2) fr_insert(gt == 0 ? p0 : p1);   // seed frontier with pair nodes
    long long base = (long long)gt * EPT;
    if (base >= N_EDGES) return;

    int d[EPT];
    if (is32) {
        const int* dp = (const int*)edge + N_EDGES;
        int4 t = *(const int4*)(dp + base);
        d[0] = t.x; d[1] = t.y; d[2] = t.z; d[3] = t.w;
    } else {
        const long long* dp = (const long long*)edge + N_EDGES;
        longlong2 a = *(const longlong2*)(dp + base);
        longlong2 b = *(const longlong2*)(dp + base + 2);
        d[0] = (int)a.x; d[1] = (int)a.y; d[2] = (int)b.x; d[3] = (int)b.y;
    }
    #pragma unroll
    for (int k = 0; k < EPT; k++) {
        int dd = d[k];
        if ((unsigned)dd >= N_NODES) continue;
        atomicAdd(&g_deg[dd], 1);
        if (dd == p0 || dd == p1) {
            int s = idx_at(edge, base + k, is32);
            if ((unsigned)s >= N_NODES) continue;
            if (dd == p0) {
                int j = atomicAdd(&g_cntA, 1);
                if (j < MAXL) g_listA[j] = s;
            }
            if (dd == p1) {
                int j = atomicAdd(&g_cntB, 1);
                if (j < MAXL) g_listB[j] = s;
            }
            fr_insert(s);
        }
    }
}

// ---------------- K2: scan dst -> fused layer-1 aggregation ----------
// for each edge (s -> d in frontier): agg[slot(d)] += rsqrt(deg[s]+1) * x[s]
__global__ void k_scan2(const void* __restrict__ edge,
                        const float* __restrict__ x) {
    int is32 = g_is32;
    int gt = blockIdx.x * blockDim.x + threadIdx.x;
    long long base = (long long)gt * EPT;
    if (base >= N_EDGES) return;

    int d[EPT];
    if (is32) {
        const int* dp = (const int*)edge + N_EDGES;
        int4 t = *(const int4*)(dp + base);
        d[0] = t.x; d[1] = t.y; d[2] = t.z; d[3] = t.w;
    } else {
        const long long* dp = (const long long*)edge + N_EDGES;
        longlong2 a = *(const longlong2*)(dp + base);
        longlong2 b = *(const longlong2*)(dp + base + 2);
        d[0] = (int)a.x; d[1] = (int)a.y; d[2] = (int)b.x; d[3] = (int)b.y;
    }
    #pragma unroll
    for (int k = 0; k < EPT; k++) {
        int dd = d[k];
        if ((unsigned)dd >= N_NODES) continue;
        int sl = g_slot[dd];
        if (sl >= 0 && sl < MAXF) {
            int s = idx_at(edge, base + k, is32);
            if ((unsigned)s >= N_NODES) continue;
            float w = rsqrtf((float)(g_deg[s] + 1));
            const float4* xr = (const float4*)(x + (size_t)s * C);
            float* ag = g_agg + (size_t)sl * C;
            #pragma unroll
            for (int c4 = 0; c4 < C / 4; c4++) {
                float4 v = __ldg(xr + c4);
                atomicAdd(ag + 4 * c4 + 0, w * v.x);
                atomicAdd(ag + 4 * c4 + 1, w * v.y);
                atomicAdd(ag + 4 * c4 + 2, w * v.z);
                atomicAdd(ag + 4 * c4 + 3, w * v.w);
            }
        }
    }
}

// ---------------- K3: layer-1 GCN (matvec) for frontier nodes ----------
// h1[v] = relu( (dv*agg + dv^2*x[v]) @ W1 + b1 )
__global__ void k_layer1(const float* __restrict__ x,
                         const float* __restrict__ W1,
                         const float* __restrict__ b1) {
    int s = blockIdx.x;
    if (s >= g_nfront || s >= MAXF) return;
    int v = g_frontier[s];
    float dv = rsqrtf((float)(g_deg[v] + 1));
    int c = threadIdx.x;                       // 64 threads, one channel each
    float y = dv * g_agg[s * C + c] + dv * dv * __ldg(&x[(size_t)v * C + c]);
    __shared__ float sy[C];
    sy[c] = y;
    __syncthreads();
    float acc = b1[c];
    #pragma unroll
    for (int k = 0; k < C; k++) acc += sy[k] * W1[k * C + c];
    g_h1[s * C + c] = fmaxf(acc, 0.0f);
}

// ---------------- K4: layer-2 GCN + fc + sigmoid (single block) ----------
__global__ void k_tail(const void* __restrict__ pair,
                       const float* __restrict__ W2,
                       const float* __restrict__ b2,
                       const float* __restrict__ fcW,
                       const float* __restrict__ fcb,
                       float* __restrict__ out) {
    int is32 = g_is32;
    int t = threadIdx.x;                       // 128 threads
    int p = t >> 6;                            // 0 or 1
    int c = t & (C - 1);
    int v = idx_at(pair, p, is32);
    __shared__ float sz[2 * C];
    __shared__ float sh2[2 * C];
    float z = 0.0f;
    if ((unsigned)v < N_NODES) {
        float dv = rsqrtf((float)(g_deg[v] + 1));
        int sv = g_slot[v];
        if (sv >= 0 && sv < MAXF) z = dv * dv * g_h1[sv * C + c];
        int cnt = (p == 0) ? min(g_cntA, MAXL) : min(g_cntB, MAXL);
        const int* list = (p == 0) ? g_listA : g_listB;
        for (int j = 0; j < cnt; j++) {
            int u = list[j];
            int su = g_slot[u];
            if (su >= 0 && su < MAXF)
                z += rsqrtf((float)(g_deg[u] + 1)) * dv * g_h1[su * C + c];
        }
    }
    sz[t] = z;
    __syncthreads();
    // matvec per half: h2[p][c] = relu(b2[c] + sum_k sz[p*C+k]*W2[k][c])
    float acc = b2[c];
    #pragma unroll
    for (int k = 0; k < C; k++) acc += sz[p * C + k] * W2[k * C + c];
    sh2[t] = fmaxf(acc, 0.0f) * fcW[t];
    __syncthreads();
    for (int s = C; s > 0; s >>= 1) {
        if (t < s) sh2[t] += sh2[t + s];
        __syncthreads();
    }
    if (t == 0) out[0] = 1.0f / (1.0f + expf(-(sh2[0] + fcb[0])));
}

// ---------------- launch ----------------
extern "C" void kernel_launch(void* const* d_in, const int* in_sizes, int n_in,
                              void* d_out, int out_size) {
    const float* x    = (const float*)d_in[0];
    const void*  edge = d_in[1];
    const void*  pair = d_in[2];
    const float* W1   = (const float*)d_in[3];
    const float* b1   = (const float*)d_in[4];
    const float* W2   = (const float*)d_in[5];
    const float* b2   = (const float*)d_in[6];
    const float* fcW  = (const float*)d_in[7];
    const float* fcb  = (const float*)d_in[8];
    float* out = (float*)d_out;

    const int scan_threads = N_EDGES / EPT;            // 400000
    const int scan_blocks  = (scan_threads + 255) / 256;

    k_init<<<(N_NODES + 511) / 512, 512>>>(edge);
    k_scan1<<<scan_blocks, 256>>>(edge, pair);
    k_scan2<<<scan_blocks, 256>>>(edge, x);
    k_layer1<<<MAXF, C>>>(x, W1, b1);
    k_tail<<<1, 2 * C>>>(pair, W2, b2, fcW, fcb, out);
}